// round 17
// baseline (speedup 1.0000x reference)
#include <cuda_runtime.h>
#include <math.h>

// Sinkhorn distance, N=M=4096, D=256, EPS=0.1, 100 iterations.
// R17 = R16 + bound tables: per-(row,128-col-chunk) and per-(col,128-row-
// chunk) maxes of -C2, precomputed once. A chunk whose upper bound
// chunkmax(potential)+chunkmax(-C) is below shift-TH_SKIP is never LOADED
// (contribution < 2^-40 -> exact in fp32). Retry ladder guarantees validity.

#define NN 4096
#define KK 256
#define SCALEF 14.4269504088896340736f   // log2(e)/EPS
#define NEG_BIG (-1e30f)
#define THREADS 1024
#define NBMAX 160
#define N_ITER 100
#define TH_SKIP 40.f
#define TH_LO   10.f
#define TH_HI   50.f
#define CLAMP   80.f

__device__ __align__(16) float g_C2[(size_t)NN * NN];     // 64 MB: C * SCALEF
__device__ __align__(16) float g_Mu[(size_t)NN * 32];     // row bound table
__device__ __align__(16) float g_MvT[(size_t)32 * NN];    // col bound table (transposed)
__device__ __align__(16) float g_u[NN];
__device__ __align__(16) float g_v[NN];
__device__ __align__(16) float g_mu[NN];                  // row max estimate
__device__ __align__(16) float g_mv[NN];                  // col max estimate
__device__ float g_xs[NN];
__device__ float g_ys[NN];
__device__ double g_dpart[NBMAX];

__device__ unsigned g_bar_count;
__device__ volatile unsigned g_bar_gen;

__device__ __forceinline__ float ex2f(float x) {
    float r; asm("ex2.approx.ftz.f32 %0, %1;" : "=f"(r) : "f"(x)); return r;
}
__device__ __forceinline__ float lg2f(float x) {
    float r; asm("lg2.approx.ftz.f32 %0, %1;" : "=f"(r) : "f"(x)); return r;
}

// R11 atomic barrier (single-line spin; proven).
__device__ __forceinline__ void grid_sync(int NB) {
    __syncthreads();
    if (threadIdx.x == 0) {
        unsigned gen = g_bar_gen;
        __threadfence();
        unsigned t = atomicAdd(&g_bar_count, 1u);
        if (t == (unsigned)(NB - 1)) {
            g_bar_count = 0;
            __threadfence();
            g_bar_gen = gen + 1;
        } else {
            while (g_bar_gen == gen) { }
        }
        __threadfence();
    }
    __syncthreads();
}

// ---------------------------------------------------------------------------
__global__ __launch_bounds__(256) void sqnorm_kernel(const float* __restrict__ X,
                                                     const float* __restrict__ Y) {
    int gw = (blockIdx.x * 256 + threadIdx.x) >> 5;
    int lane = threadIdx.x & 31;
    const float* src = (gw < NN) ? (X + (size_t)gw * KK) : (Y + (size_t)(gw - NN) * KK);
    float s = 0.f;
    #pragma unroll
    for (int c = 0; c < KK; c += 32) {
        float a = src[c + lane];
        s = fmaf(a, a, s);
    }
    #pragma unroll
    for (int o = 16; o; o >>= 1) s += __shfl_xor_sync(0xffffffffu, s, o);
    if (lane == 0) {
        if (gw < NN) g_xs[gw] = s; else g_ys[gw - NN] = s;
    }
}

__global__ void init_kernel() {
    int i = blockIdx.x * 256 + threadIdx.x;
    if (i < NN) { g_v[i] = 0.f; g_mu[i] = NEG_BIG; g_mv[i] = NEG_BIG; }
    if (i == 0) { g_bar_count = 0; g_bar_gen = 0; }
}

// ---------------------------------------------------------------------------
// C2 = (|x|^2 + |y|^2 - 2 x.y) * SCALEF  (fp32 FFMA GEMM, k-tile prefetch)
__global__ __launch_bounds__(256) void gemm_kernel(const float* __restrict__ X,
                                                   const float* __restrict__ Y) {
    __shared__ float As[8][128];
    __shared__ float Bs[8][128];
    const int tid = threadIdx.x;
    const int bx = blockIdx.x;
    const int by = blockIdx.y;
    const int ar = tid >> 1;
    const int ak = (tid & 1) * 4;
    const int tx = tid & 15;
    const int ty = tid >> 4;

    const float* xp = X + (size_t)(by * 128 + ar) * KK + ak;
    const float* yp = Y + (size_t)(bx * 128 + ar) * KK + ak;

    float acc[8][8];
    #pragma unroll
    for (int i = 0; i < 8; ++i)
        #pragma unroll
        for (int j = 0; j < 8; ++j) acc[i][j] = 0.f;

    float4 av = *(const float4*)(xp);
    float4 bv = *(const float4*)(yp);

    for (int kt = 0; kt < KK; kt += 8) {
        __syncthreads();
        As[ak + 0][ar] = av.x; As[ak + 1][ar] = av.y;
        As[ak + 2][ar] = av.z; As[ak + 3][ar] = av.w;
        Bs[ak + 0][ar] = bv.x; Bs[ak + 1][ar] = bv.y;
        Bs[ak + 2][ar] = bv.z; Bs[ak + 3][ar] = bv.w;
        __syncthreads();
        if (kt + 8 < KK) {
            av = *(const float4*)(xp + kt + 8);
            bv = *(const float4*)(yp + kt + 8);
        }
        #pragma unroll
        for (int k = 0; k < 8; ++k) {
            float a[8], b[8];
            *(float4*)(a)     = *(const float4*)&As[k][ty * 8];
            *(float4*)(a + 4) = *(const float4*)&As[k][ty * 8 + 4];
            *(float4*)(b)     = *(const float4*)&Bs[k][tx * 8];
            *(float4*)(b + 4) = *(const float4*)&Bs[k][tx * 8 + 4];
            #pragma unroll
            for (int i = 0; i < 8; ++i)
                #pragma unroll
                for (int j = 0; j < 8; ++j)
                    acc[i][j] = fmaf(a[i], b[j], acc[i][j]);
        }
    }

    const int gi0 = by * 128 + ty * 8;
    const int gj0 = bx * 128 + tx * 8;
    float yv[8];
    #pragma unroll
    for (int j = 0; j < 8; ++j) yv[j] = g_ys[gj0 + j];
    #pragma unroll
    for (int i = 0; i < 8; ++i) {
        float xs = g_xs[gi0 + i];
        float4 o0, o1;
        o0.x = (xs + yv[0] - 2.f * acc[i][0]) * SCALEF;
        o0.y = (xs + yv[1] - 2.f * acc[i][1]) * SCALEF;
        o0.z = (xs + yv[2] - 2.f * acc[i][2]) * SCALEF;
        o0.w = (xs + yv[3] - 2.f * acc[i][3]) * SCALEF;
        o1.x = (xs + yv[4] - 2.f * acc[i][4]) * SCALEF;
        o1.y = (xs + yv[5] - 2.f * acc[i][5]) * SCALEF;
        o1.z = (xs + yv[6] - 2.f * acc[i][6]) * SCALEF;
        o1.w = (xs + yv[7] - 2.f * acc[i][7]) * SCALEF;
        float* dst = g_C2 + (size_t)(gi0 + i) * NN + gj0;
        *(float4*)(dst)     = o0;
        *(float4*)(dst + 4) = o1;
    }
}

// ---------------------------------------------------------------------------
// bound tables: max of (-C2) over 128-elem chunks, row-wise and column-wise.
__global__ __launch_bounds__(256) void chunkmax_u_kernel() {
    int gw = (blockIdx.x * 256 + threadIdx.x) >> 5;   // 131072 warp-tasks
    int lane = threadIdx.x & 31;
    int row = gw >> 5, ch = gw & 31;
    float4 v = __ldg((const float4*)(g_C2 + (size_t)row * NN + ch * 128 + lane * 4));
    float m = fmaxf(fmaxf(-v.x, -v.y), fmaxf(-v.z, -v.w));
    #pragma unroll
    for (int o = 16; o; o >>= 1) m = fmaxf(m, __shfl_xor_sync(0xffffffffu, m, o));
    if (lane == 0) g_Mu[(size_t)row * 32 + ch] = m;
}

__global__ __launch_bounds__(256) void chunkmax_v_kernel() {
    int b = blockIdx.x;                               // 4096 blocks
    int g = b >> 5, cb = b & 31;
    int wid = threadIdx.x >> 5, lane = threadIdx.x & 31;
    int col = g * 32 + lane;
    int row0 = cb * 128 + wid * 16;
    float m = NEG_BIG;
    #pragma unroll
    for (int t = 0; t < 16; ++t)
        m = fmaxf(m, -__ldg(&g_C2[(size_t)(row0 + t) * NN + col]));
    __shared__ float sm[8][33];
    sm[wid][lane] = m;
    __syncthreads();
    if (wid == 0) {
        float mm = sm[0][lane];
        #pragma unroll
        for (int w = 1; w < 8; ++w) mm = fmaxf(mm, sm[w][lane]);
        g_MvT[(size_t)cb * NN + col] = mm;
    }
}

// ---------------------------------------------------------------------------
// one 128-elem subchunk: load + scan + vote + exp
#define SUB1(off)                                                              \
    {                                                                          \
        float4 Cx = __ldg((const float4*)(Crow + (off) + lane * 4));           \
        float4 V = *(const float4*)&svec[(off) + lane * 4];                    \
        float t0 = V.x - Cx.x, t1 = V.y - Cx.y;                                \
        float t2 = V.z - Cx.z, t3 = V.w - Cx.w;                                \
        float mc = fmaxf(fmaxf(t0, t1), fmaxf(t2, t3));                        \
        mrun = fmaxf(mrun, mc);                                                \
        if (__any_sync(0xffffffffu, mc >= thr)) {                              \
            s += (ex2f(fminf(t0 - shift, CLAMP)) + ex2f(fminf(t1 - shift, CLAMP)))   \
               + (ex2f(fminf(t2 - shift, CLAMP)) + ex2f(fminf(t3 - shift, CLAMP)));  \
        }                                                                      \
    }

__global__ __launch_bounds__(THREADS, 1) void sinkhorn_persistent(int NB, float* __restrict__ out) {
    const int tid = threadIdx.x;
    const int bid = blockIdx.x;
    const int lane = tid & 31;
    const int wid = tid >> 5;

    __shared__ float svec[NN];          // 16 KB: dual-potential cache
    __shared__ float schmax[32];        // 128-elem chunk maxes of potential
    __shared__ float sm_m[32][33];
    __shared__ float sm_s[32][33];
    __shared__ float sshift[32];
    __shared__ int   sfail;
    __shared__ float sred[32];

    for (int it = 0; it < N_ITER; ++it) {
        // ---- u-pass ----
        for (int i = tid; i < NN; i += THREADS) svec[i] = g_v[i];
        __syncthreads();
        {   // chunk maxes of v: warp w handles chunk w
            float4 x = *(const float4*)&svec[(wid << 7) + (lane << 2)];
            float m = fmaxf(fmaxf(x.x, x.y), fmaxf(x.z, x.w));
            #pragma unroll
            for (int o = 16; o; o >>= 1) m = fmaxf(m, __shfl_xor_sync(0xffffffffu, m, o));
            if (lane == 0) schmax[wid] = m;
        }
        __syncthreads();

        for (int row = bid + wid * NB; row < NN; row += 32 * NB) {
            const float* Crow = g_C2 + (size_t)row * NN;
            // lane l <-> chunk l upper bound (constant across attempts)
            float bnd = schmax[lane] + __ldg(&g_Mu[(size_t)row * 32 + lane]);
            float shift = g_mu[row];
            float Mrun, Ssum;
            #pragma unroll 1
            for (int attempt = 0; attempt < 6; ++attempt) {
                float mrun = NEG_BIG, s = 0.f;
                const float thr = shift - TH_SKIP;
                #pragma unroll 1
                for (int c0 = 0; c0 < NN; c0 += 512) {
                    int sc0 = c0 >> 7;
                    float b0 = __shfl_sync(0xffffffffu, bnd, sc0);
                    float b1 = __shfl_sync(0xffffffffu, bnd, sc0 + 1);
                    float b2 = __shfl_sync(0xffffffffu, bnd, sc0 + 2);
                    float b3 = __shfl_sync(0xffffffffu, bnd, sc0 + 3);
                    if (!(b0 >= thr || b1 >= thr || b2 >= thr || b3 >= thr)) continue;
                    if (b0 >= thr) SUB1(c0)
                    if (b1 >= thr) SUB1(c0 + 128)
                    if (b2 >= thr) SUB1(c0 + 256)
                    if (b3 >= thr) SUB1(c0 + 384)
                }
                Mrun = mrun; Ssum = s;
                #pragma unroll
                for (int o = 16; o; o >>= 1) {
                    Mrun = fmaxf(Mrun, __shfl_xor_sync(0xffffffffu, Mrun, o));
                    Ssum += __shfl_xor_sync(0xffffffffu, Ssum, o);
                }
                if (Mrun >= shift - TH_LO && Mrun <= shift + TH_HI) break;
                shift = Mrun;
            }
            if (lane == 0) {
                g_u[row] = -(shift + lg2f(Ssum));
                g_mu[row] = Mrun;
            }
        }
        grid_sync(NB);

        // ---- v-pass ----
        for (int i = tid; i < NN; i += THREADS) svec[i] = g_u[i];
        __syncthreads();
        {   // chunk maxes of u
            float4 x = *(const float4*)&svec[(wid << 7) + (lane << 2)];
            float m = fmaxf(fmaxf(x.x, x.y), fmaxf(x.z, x.w));
            #pragma unroll
            for (int o = 16; o; o >>= 1) m = fmaxf(m, __shfl_xor_sync(0xffffffffu, m, o));
            if (lane == 0) schmax[wid] = m;
        }
        __syncthreads();

        for (int g = bid; g < NN / 32; g += NB) {
            const int j0 = g << 5;
            const int c = lane;
            const int r = wid;
            if (tid < 32) sshift[tid] = g_mv[j0 + tid];
            if (tid == 0) sfail = 0;
            __syncthreads();
            #pragma unroll 1
            for (int attempt = 0; attempt < 6; ++attempt) {
                float shift = sshift[c];
                const float thr = shift - TH_SKIP;
                float mrun = NEG_BIG, s = 0.f;
                #pragma unroll 1
                for (int q0 = 0; q0 < NN; q0 += 512) {
                    int cb0 = q0 >> 7;
                    float bb[4];
                    #pragma unroll
                    for (int k = 0; k < 4; ++k)
                        bb[k] = __ldg(&g_MvT[(size_t)(cb0 + k) * NN + j0 + c]) + schmax[cb0 + k];
                    #pragma unroll
                    for (int k = 0; k < 4; ++k) {
                        if (!__any_sync(0xffffffffu, bb[k] >= thr)) continue;
                        const float* p = g_C2 + (size_t)(q0 + 128 * k + r) * NN + j0 + c;
                        const float* up = &svec[q0 + 128 * k + r];
                        float t0 = up[0]  - __ldg(p);
                        float t1 = up[32] - __ldg(p + (size_t)32 * NN);
                        float t2 = up[64] - __ldg(p + (size_t)64 * NN);
                        float t3 = up[96] - __ldg(p + (size_t)96 * NN);
                        float mc = fmaxf(fmaxf(t0, t1), fmaxf(t2, t3));
                        mrun = fmaxf(mrun, mc);
                        if (__any_sync(0xffffffffu, mc >= thr)) {
                            s += (ex2f(fminf(t0 - shift, CLAMP)) + ex2f(fminf(t1 - shift, CLAMP)))
                               + (ex2f(fminf(t2 - shift, CLAMP)) + ex2f(fminf(t3 - shift, CLAMP)));
                        }
                    }
                }
                sm_m[r][c] = mrun;
                sm_s[r][c] = s;
                __syncthreads();
                {   // warp wid merges column wid
                    float mm = sm_m[lane][wid];
                    float ss = sm_s[lane][wid];
                    #pragma unroll
                    for (int o = 16; o; o >>= 1) {
                        mm = fmaxf(mm, __shfl_xor_sync(0xffffffffu, mm, o));
                        ss += __shfl_xor_sync(0xffffffffu, ss, o);
                    }
                    float sc = sshift[wid];
                    bool ok = (mm >= sc - TH_LO && mm <= sc + TH_HI);
                    if (lane == 0) {
                        if (ok) {
                            g_v[j0 + wid] = -(sc + lg2f(ss));
                            g_mv[j0 + wid] = mm;
                        } else {
                            sshift[wid] = mm;
                            sfail = 1;
                        }
                    }
                }
                __syncthreads();
                if (!sfail) break;
                if (tid == 0) sfail = 0;
                __syncthreads();
            }
            __syncthreads();
        }
        grid_sync(NB);
    }

    // ---- final cost: sum P*C / N  (warp-per-row, full exp) ----
    {
        for (int i = tid; i < NN; i += THREADS) svec[i] = g_v[i];
        __syncthreads();
        float acc = 0.f;
        for (int row = bid + wid * NB; row < NN; row += 32 * NB) {
            const float u2 = g_u[row];
            const float* Crow = g_C2 + (size_t)row * NN;
            #pragma unroll 4
            for (int c0 = 0; c0 < NN; c0 += 128) {
                int cc = c0 + lane * 4;
                float4 C4 = __ldg((const float4*)(Crow + cc));
                float4 V4 = *(const float4*)&svec[cc];
                acc = fmaf(ex2f(u2 + V4.x - C4.x), C4.x, acc);
                acc = fmaf(ex2f(u2 + V4.y - C4.y), C4.y, acc);
                acc = fmaf(ex2f(u2 + V4.z - C4.z), C4.z, acc);
                acc = fmaf(ex2f(u2 + V4.w - C4.w), C4.w, acc);
            }
        }
        #pragma unroll
        for (int o = 16; o; o >>= 1) acc += __shfl_xor_sync(0xffffffffu, acc, o);
        __syncthreads();
        if (lane == 0) sred[wid] = acc;
        __syncthreads();
        if (wid == 0) {
            float s = sred[lane];
            #pragma unroll
            for (int o = 16; o; o >>= 1) s += __shfl_xor_sync(0xffffffffu, s, o);
            if (lane == 0) g_dpart[bid] = (double)s;
        }
        grid_sync(NB);
        if (bid == 0 && tid == 0) {
            double S = 0.0;
            for (int b = 0; b < NB; ++b) S += g_dpart[b];
            out[0] = (float)(S / ((double)SCALEF * (double)NN));
        }
    }
}

// ---------------------------------------------------------------------------
extern "C" void kernel_launch(void* const* d_in, const int* in_sizes, int n_in,
                              void* d_out, int out_size) {
    const float* x = (const float*)d_in[0];
    const float* y = (const float*)d_in[1];
    float* out = (float*)d_out;

    int dev = 0;
    cudaGetDevice(&dev);
    int sm = 148;
    cudaDeviceGetAttribute(&sm, cudaDevAttrMultiProcessorCount, dev);
    int NB = sm < NBMAX ? sm : NBMAX;

    sqnorm_kernel<<<1024, 256>>>(x, y);
    init_kernel<<<16, 256>>>();
    gemm_kernel<<<dim3(32, 32), 256>>>(x, y);
    chunkmax_u_kernel<<<16384, 256>>>();
    chunkmax_v_kernel<<<4096, 256>>>();
    sinkhorn_persistent<<<NB, THREADS>>>(NB, out);
}